// round 8
// baseline (speedup 1.0000x reference)
#include <cuda_runtime.h>

// Depthwise Conv1d: B=32, C=128, L=8192, kernel=3, stride=1, pad=1, fp32.
// out[b,c,l] = w[c,0]*x[b,c,l-1] + w[c,1]*x[b,c,l] + w[c,2]*x[b,c,l+1] + bias[c]
//
// R8: single-wave persistent version of R4. 1024 blocks x 256 threads
// (fits in one wave at <=7 blocks/SM), each thread processes 32 float4
// as 8 outer iterations of the proven front-batched ITER=4 body.
// Grid stride = 262,144 float4 = exactly 128 rows, so each thread keeps
// the SAME within-row position j and SAME channel c for all 32 tiles:
// taps load once, edge predicates are uniform, index ALU is minimal.
// Halo elements are scalar L1-hit loads (measured cheapest variant).

#define BATCH 32
#define CHANS 128
#define LEN   8192
#define LEN4  (LEN / 4)          // 2048 float4 per row
#define ROWS  (BATCH * CHANS)    // 4096
#define NTHREADS 256
#define NBLOCKS  1024
#define STRIDE4  (NBLOCKS * NTHREADS)        // 262,144 float4 = 128 rows
#define OUTER 8
#define ILP   4
// total = STRIDE4 * OUTER * ILP = 8,388,608 = ROWS*LEN4  (exact)

__global__ __launch_bounds__(NTHREADS)
void dwconv1d_kernel(const float* __restrict__ x,
                     const float* __restrict__ w,
                     const float* __restrict__ bias,
                     float* __restrict__ out)
{
    const unsigned int gid = blockIdx.x * NTHREADS + threadIdx.x;
    const unsigned int j   = gid & (LEN4 - 1);   // same for every tile of this thread
    const unsigned int c   = (gid >> 11) & (CHANS - 1);

    const float w0 = __ldg(&w[c * 3 + 0]);
    const float w1 = __ldg(&w[c * 3 + 1]);
    const float w2 = __ldg(&w[c * 3 + 2]);
    const float bb = __ldg(&bias[c]);

    const bool has_left  = (j != 0);
    const bool has_right = (j != LEN4 - 1);

    const float4* x4 = reinterpret_cast<const float4*>(x);
    float4*       o4 = reinterpret_cast<float4*>(out);

#pragma unroll
    for (int k = 0; k < OUTER; k++) {
        const unsigned int base = gid + (unsigned int)(k * ILP) * STRIDE4;

        // front-batched vector loads (4 outstanding LDG.128, coalesced)
        float4 v[ILP];
#pragma unroll
        for (int i = 0; i < ILP; i++)
            v[i] = x4[base + i * STRIDE4];

        // halo scalars (L1 hits; predicates uniform per thread)
        float l[ILP], r[ILP];
#pragma unroll
        for (int i = 0; i < ILP; i++) {
            const float* xe = x + 4u * (size_t)(base + i * STRIDE4);
            l[i] = has_left  ? __ldg(xe - 1) : 0.0f;
            r[i] = has_right ? __ldg(xe + 4) : 0.0f;
        }

        // compute + store
#pragma unroll
        for (int i = 0; i < ILP; i++) {
            float4 o;
            o.x = fmaf(w0, l[i],    fmaf(w1, v[i].x, fmaf(w2, v[i].y, bb)));
            o.y = fmaf(w0, v[i].x,  fmaf(w1, v[i].y, fmaf(w2, v[i].z, bb)));
            o.z = fmaf(w0, v[i].y,  fmaf(w1, v[i].z, fmaf(w2, v[i].w, bb)));
            o.w = fmaf(w0, v[i].z,  fmaf(w1, v[i].w, fmaf(w2, r[i],   bb)));
            o4[base + i * STRIDE4] = o;
        }
    }
}

extern "C" void kernel_launch(void* const* d_in, const int* in_sizes, int n_in,
                              void* d_out, int out_size)
{
    const float* x    = (const float*)d_in[0];
    const float* w    = (const float*)d_in[1];
    const float* bias = (const float*)d_in[2];
    float* out        = (float*)d_out;

    dwconv1d_kernel<<<NBLOCKS, NTHREADS>>>(x, w, bias, out);
}

// round 9
// speedup vs baseline: 1.0435x; 1.0435x over previous
#include <cuda_runtime.h>
#include <cuda_pipeline.h>

// Depthwise Conv1d: B=32, C=128, L=8192, kernel=3, stride=1, pad=1, fp32.
// out[b,c,l] = w[c,0]*x[b,c,l-1] + w[c,1]*x[b,c,l] + w[c,2]*x[b,c,l+1] + bias[c]
//
// R9: cp.async row-in-smem kernel. One block per (b,c) row (4096 blocks,
// 256 threads). The whole 32KB row is brought into shared memory with
// 8 cp.async(16B) per thread -- async copies need NO destination registers,
// so MLP=8/thread with regs ~28 and high occupancy (6 blocks/SM).
// No gmem halo loads at all: row-boundary halos are zero-padded smem slots,
// interior halos are cheap LDS. Output stores are coalesced STG.128.

#define LEN   8192
#define LEN4  (LEN / 4)     // 2048 float4 per row
#define CHANS 128
#define ROWS  4096
#define NTHREADS 256
#define TILES 8             // LEN4 / NTHREADS float4 per thread

__global__ __launch_bounds__(NTHREADS)
void dwconv1d_kernel(const float* __restrict__ x,
                     const float* __restrict__ w,
                     const float* __restrict__ bias,
                     float* __restrict__ out)
{
    // Row data lives at s[4 .. 4+LEN); s[3] and s[4+LEN] are the zero pads.
    // Offset 4 floats = 16B keeps LDS.128 alignment.
    __shared__ __align__(16) float s[LEN + 8];

    const unsigned int row = blockIdx.x;
    const unsigned int c   = row & (CHANS - 1);
    const unsigned int tid = threadIdx.x;

    const float4* xrow = reinterpret_cast<const float4*>(x) + (size_t)row * LEN4;

    // Zero-pad boundary slots (before the sync that guards compute).
    if (tid == 0) {
        s[3]       = 0.0f;
        s[4 + LEN] = 0.0f;
    }

    // ---- async load of the full row: 8 x 16B per thread, coalesced ----
#pragma unroll
    for (int k = 0; k < TILES; k++) {
        unsigned int p = tid + k * NTHREADS;          // float4 index in row
        __pipeline_memcpy_async(&s[4 + 4 * p], &xrow[p], 16);
    }
    __pipeline_commit();

    // Per-channel taps (uniform across block -> broadcast)
    const float w0 = __ldg(&w[c * 3 + 0]);
    const float w1 = __ldg(&w[c * 3 + 1]);
    const float w2 = __ldg(&w[c * 3 + 2]);
    const float bb = __ldg(&bias[c]);

    __pipeline_wait_prior(0);
    __syncthreads();

    // ---- compute from smem + coalesced stores ----
    float4* orow = reinterpret_cast<float4*>(out) + (size_t)row * LEN4;

#pragma unroll
    for (int k = 0; k < TILES; k++) {
        unsigned int p = tid + k * NTHREADS;
        const float* sp = &s[4 * p];          // sp[0]=left, sp[1..4]=v, sp[5]=right
        float  l = sp[3];
        float4 v = *reinterpret_cast<const float4*>(sp + 4);
        float  r = sp[8];

        float4 o;
        o.x = fmaf(w0, l,   fmaf(w1, v.x, fmaf(w2, v.y, bb)));
        o.y = fmaf(w0, v.x, fmaf(w1, v.y, fmaf(w2, v.z, bb)));
        o.z = fmaf(w0, v.y, fmaf(w1, v.z, fmaf(w2, v.w, bb)));
        o.w = fmaf(w0, v.z, fmaf(w1, v.w, fmaf(w2, r,   bb)));
        orow[p] = o;
    }
}

extern "C" void kernel_launch(void* const* d_in, const int* in_sizes, int n_in,
                              void* d_out, int out_size)
{
    const float* x    = (const float*)d_in[0];
    const float* w    = (const float*)d_in[1];
    const float* bias = (const float*)d_in[2];
    float* out        = (float*)d_out;

    dwconv1d_kernel<<<ROWS, NTHREADS>>>(x, w, bias, out);
}